// round 3
// baseline (speedup 1.0000x reference)
#include <cuda_runtime.h>
#include <cstdint>
#include <cstddef>

// ---------------------------------------------------------------------------
// Problem constants
// ---------------------------------------------------------------------------
#define VOCAB 50257
#define DMODEL 768
#define NEXP 4
#define RRANK 32
#define BATCH 4
#define SEQ 512
#define NROWS (BATCH * SEQ)   // 2048

// ---------------------------------------------------------------------------
// Scratch (static device buffers; no cudaMalloc allowed). 256B-aligned so
// vectorized (float4) access is always legal.
// ---------------------------------------------------------------------------
__device__ __align__(256) float g_x[NROWS * DMODEL];        // embedded inputs
__device__ __align__(256) float g_h[NROWS * DMODEL];        // layernormed stream
__device__ __align__(256) float g_P[NROWS * NEXP * RRANK];  // x @ W_in
__device__ __align__(256) float g_C[NROWS * RRANK];         // winner candidates
__device__ __align__(256) int   g_E[NROWS];                 // winner expert idx

__device__ __forceinline__ uint32_t f32_to_tf32(float f) {
    uint32_t o;
    asm("cvt.rna.tf32.f32 %0, %1;" : "=r"(o) : "f"(f));
    return o;
}

// ---------------------------------------------------------------------------
// Kernel 1: embedding gather + routing scores + input projection (all experts)
// ---------------------------------------------------------------------------
__global__ __launch_bounds__(160) void k_embed_route(
    const int* __restrict__ idx, const float* __restrict__ Wemb,
    const float* __restrict__ G, const float* __restrict__ Win) {
    __shared__ float xs[8][DMODEL];
    __shared__ float ssc[8][NEXP];
    __shared__ int tok[8];
    const int tid = threadIdx.x;
    const int row0 = blockIdx.x * 8;

    if (tid < 8) tok[tid] = idx[row0 + tid];
    __syncthreads();
    for (int i = tid; i < 8 * DMODEL; i += 160) {
        int rr = i / DMODEL, d = i - rr * DMODEL;
        float v = Wemb[(size_t)tok[rr] * DMODEL + d];
        xs[rr][d] = v;
        g_x[(size_t)(row0 + rr) * DMODEL + d] = v;
    }
    __syncthreads();

    const int j = tid;
    if (j < 132) {
        float acc[8];
#pragma unroll
        for (int rr = 0; rr < 8; rr++) acc[rr] = 0.0f;
        const float* wp;
        int stride;
        if (j < 128) { int e = j >> 5, r = j & 31; wp = Win + (size_t)e * DMODEL * RRANK + r; stride = RRANK; }
        else         { wp = G + (size_t)(j - 128) * DMODEL; stride = 1; }
        for (int d = 0; d < DMODEL; d += 4) {
            float w0 = wp[(size_t)d * stride];
            float w1 = wp[(size_t)(d + 1) * stride];
            float w2 = wp[(size_t)(d + 2) * stride];
            float w3 = wp[(size_t)(d + 3) * stride];
#pragma unroll
            for (int rr = 0; rr < 8; rr++) {
                float4 xv = *(const float4*)&xs[rr][d];
                acc[rr] = fmaf(xv.x, w0, acc[rr]);
                acc[rr] = fmaf(xv.y, w1, acc[rr]);
                acc[rr] = fmaf(xv.z, w2, acc[rr]);
                acc[rr] = fmaf(xv.w, w3, acc[rr]);
            }
        }
        if (j < 128) {
#pragma unroll
            for (int rr = 0; rr < 8; rr++)
                g_P[(size_t)(row0 + rr) * (NEXP * RRANK) + j] = acc[rr];
        } else {
#pragma unroll
            for (int rr = 0; rr < 8; rr++) ssc[rr][j - 128] = acc[rr];
        }
    }
    __syncthreads();
    if (tid < 8) {
        float best = ssc[tid][0];
        int be = 0;
#pragma unroll
        for (int e = 1; e < NEXP; e++)
            if (ssc[tid][e] > best) { best = ssc[tid][e]; be = e; }
        g_E[row0 + tid] = be;
    }
}

// ---------------------------------------------------------------------------
// Kernel 2: sequential recurrence over time (1 block, 1 warp per batch).
// ---------------------------------------------------------------------------
#define STEP_CASE(ST, WR) {                                                    \
    float a0 = 0.f, a1 = 0.f, a2 = 0.f, a3 = 0.f;                              \
    _Pragma("unroll")                                                          \
    for (int k = 0; k < 8; k++) {                                              \
        a0 = fmaf(__shfl_sync(0xffffffffu, ST, k     ), WR[k     ], a0);       \
        a1 = fmaf(__shfl_sync(0xffffffffu, ST, k +  8), WR[k +  8], a1);       \
        a2 = fmaf(__shfl_sync(0xffffffffu, ST, k + 16), WR[k + 16], a2);       \
        a3 = fmaf(__shfl_sync(0xffffffffu, ST, k + 24), WR[k + 24], a3);       \
    }                                                                          \
    cand = tanhf(p_cur + ((a0 + a1) + (a2 + a3)));                             \
    ST = cand; }

__global__ __launch_bounds__(128, 1) void k_scan(const float* __restrict__ Wrec) {
    const int tid = threadIdx.x;
    const int b = tid >> 5;
    const int o = tid & 31;

    float wr0[32], wr1[32], wr2[32], wr3[32];
#pragma unroll
    for (int k = 0; k < 32; k++) {
        wr0[k] = Wrec[          k * 32 + o];
        wr1[k] = Wrec[1024 +    k * 32 + o];
        wr2[k] = Wrec[2048 +    k * 32 + o];
        wr3[k] = Wrec[3072 +    k * 32 + o];
    }
    float st0 = 0.f, st1 = 0.f, st2 = 0.f, st3 = 0.f;

    const int base = b * SEQ;
    int   e_cur = g_E[base];
    int   e_nxt = g_E[base + 1];
    float p_cur = g_P[(size_t)base * 128 + e_cur * 32 + o];

    for (int t = 0; t < SEQ; t++) {
        float p_nxt = 0.f;
        int   e_nn = 0;
        if (t + 1 < SEQ) p_nxt = g_P[(size_t)(base + t + 1) * 128 + e_nxt * 32 + o];
        if (t + 2 < SEQ) e_nn = g_E[base + t + 2];

        float cand;
        switch (e_cur) {
            case 0: STEP_CASE(st0, wr0); break;
            case 1: STEP_CASE(st1, wr1); break;
            case 2: STEP_CASE(st2, wr2); break;
            default: STEP_CASE(st3, wr3); break;
        }
        g_C[(size_t)(base + t) * 32 + o] = cand;

        p_cur = p_nxt; e_cur = e_nxt; e_nxt = e_nn;
    }
}

// ---------------------------------------------------------------------------
// Kernel 3: output projection + residual + LayerNorm  (block per row)
// ---------------------------------------------------------------------------
__global__ __launch_bounds__(256) void k_outln(
    const float* __restrict__ Wout, const float* __restrict__ gamma,
    const float* __restrict__ beta) {
    __shared__ float csh[32];
    __shared__ float rs[8], rs2[8];
    const int row = blockIdx.x;
    const int tid = threadIdx.x;
    if (tid < 32) csh[tid] = g_C[(size_t)row * 32 + tid];
    const int e = g_E[row];
    __syncthreads();

    const float* wb = Wout + (size_t)e * RRANK * DMODEL;
    float y[3];
    float s = 0.f, s2 = 0.f;
#pragma unroll
    for (int ii = 0; ii < 3; ii++) {
        int d = tid + ii * 256;
        float acc = g_x[(size_t)row * DMODEL + d];
#pragma unroll
        for (int r = 0; r < 32; r++)
            acc = fmaf(csh[r], wb[r * DMODEL + d], acc);
        y[ii] = acc;
        s += acc;
        s2 = fmaf(acc, acc, s2);
    }
#pragma unroll
    for (int off = 16; off; off >>= 1) {
        s  += __shfl_xor_sync(0xffffffffu, s, off);
        s2 += __shfl_xor_sync(0xffffffffu, s2, off);
    }
    if ((tid & 31) == 0) { rs[tid >> 5] = s; rs2[tid >> 5] = s2; }
    __syncthreads();
    float S = 0.f, S2 = 0.f;
#pragma unroll
    for (int w = 0; w < 8; w++) { S += rs[w]; S2 += rs2[w]; }
    const float mean = S * (1.0f / DMODEL);
    const float var = S2 * (1.0f / DMODEL) - mean * mean;
    const float inv = rsqrtf(var + 1e-5f);
#pragma unroll
    for (int ii = 0; ii < 3; ii++) {
        int d = tid + ii * 256;
        g_h[(size_t)row * DMODEL + d] = (y[ii] - mean) * inv * gamma[d] + beta[d];
    }
}

// ---------------------------------------------------------------------------
// Kernel 4: logits = h @ W_emb^T via legacy mma.sync tf32 (sm_103-portable).
//   CTA 128x128 tile, K chunks of 32, register-staged double buffer.
//   Smem stride 36 words => tf32 fragment LDS loads are bank-conflict-free.
//   Epilogue uses scalar 4B stores only: VOCAB is odd, so row*VOCAB+col has
//   no 8B alignment guarantee (float2 stores here -> misaligned address).
// ---------------------------------------------------------------------------
#define GTM 128
#define GTN 128
#define GKB 32
#define NKB (DMODEL / GKB)    // 24
#define ASTR 36               // words per row in smem
#define TILE_WORDS (GTM * ASTR)
#define GEMM_SMEM (4 * TILE_WORDS * 4)   // A[2] + B[2] stages, bytes

__device__ __forceinline__ void mma_tf32_16n8k8(
    float* c, const uint32_t* a, const uint32_t* b) {
    asm volatile(
        "mma.sync.aligned.m16n8k8.row.col.f32.tf32.tf32.f32 "
        "{%0,%1,%2,%3}, {%4,%5,%6,%7}, {%8,%9}, {%0,%1,%2,%3};"
        : "+f"(c[0]), "+f"(c[1]), "+f"(c[2]), "+f"(c[3])
        : "r"(a[0]), "r"(a[1]), "r"(a[2]), "r"(a[3]), "r"(b[0]), "r"(b[1]));
}

__global__ __launch_bounds__(256) void k_gemm(
    const float* __restrict__ A, const float* __restrict__ Bw,
    float* __restrict__ C) {
    extern __shared__ float sm[];
    float* As = sm;                      // [2][128*36]
    float* Bs = sm + 2 * TILE_WORDS;     // [2][128*36]

    const int tid = threadIdx.x;
    const int wid = tid >> 5, lane = tid & 31;
    const int wm = wid & 1, wn = wid >> 1;       // warp grid 2(m) x 4(n)
    const int lr = lane >> 2, lc = lane & 3;
    const int m0 = blockIdx.x * GTM;
    const int n0 = blockIdx.y * GTN;

    float acc[4][4][4];
#pragma unroll
    for (int mf = 0; mf < 4; mf++)
#pragma unroll
        for (int nf = 0; nf < 4; nf++)
#pragma unroll
            for (int q = 0; q < 4; q++) acc[mf][nf][q] = 0.0f;

    float4 ra[4], rb[4];

    // --- stage 0 global loads ---
#pragma unroll
    for (int i = 0; i < 4; i++) {
        int j = tid + i * 256;
        int m = j >> 3, k4 = j & 7;
        ra[i] = *(const float4*)(A + (size_t)(m0 + m) * DMODEL + k4 * 4);
        int rn = n0 + m;
        rb[i] = (rn < VOCAB)
                    ? *(const float4*)(Bw + (size_t)rn * DMODEL + k4 * 4)
                    : make_float4(0.f, 0.f, 0.f, 0.f);
    }

    for (int kb = 0; kb < NKB; kb++) {
        const int st = kb & 1;
        // --- store staged regs to smem (with rna tf32 rounding) ---
#pragma unroll
        for (int i = 0; i < 4; i++) {
            int j = tid + i * 256;
            int m = j >> 3, k4 = j & 7;
            uint4 t;
            t.x = f32_to_tf32(ra[i].x); t.y = f32_to_tf32(ra[i].y);
            t.z = f32_to_tf32(ra[i].z); t.w = f32_to_tf32(ra[i].w);
            *(uint4*)(As + st * TILE_WORDS + m * ASTR + k4 * 4) = t;
            t.x = f32_to_tf32(rb[i].x); t.y = f32_to_tf32(rb[i].y);
            t.z = f32_to_tf32(rb[i].z); t.w = f32_to_tf32(rb[i].w);
            *(uint4*)(Bs + st * TILE_WORDS + m * ASTR + k4 * 4) = t;
        }
        __syncthreads();

        // --- prefetch next stage into regs (latency hidden by compute) ---
        if (kb + 1 < NKB) {
#pragma unroll
            for (int i = 0; i < 4; i++) {
                int j = tid + i * 256;
                int m = j >> 3, k4 = j & 7;
                ra[i] = *(const float4*)(A + (size_t)(m0 + m) * DMODEL +
                                         (kb + 1) * GKB + k4 * 4);
                int rn = n0 + m;
                rb[i] = (rn < VOCAB)
                            ? *(const float4*)(Bw + (size_t)rn * DMODEL +
                                               (kb + 1) * GKB + k4 * 4)
                            : make_float4(0.f, 0.f, 0.f, 0.f);
            }
        }

        // --- compute on current stage ---
        const float* as = As + st * TILE_WORDS + wm * 64 * ASTR;
        const float* bs = Bs + st * TILE_WORDS + wn * 32 * ASTR;
#pragma unroll
        for (int s = 0; s < 4; s++) {
            uint32_t af[4][4], bf[4][2];
#pragma unroll
            for (int mf = 0; mf < 4; mf++) {
                const float* ap = as + (mf * 16 + lr) * ASTR + s * 8 + lc;
                af[mf][0] = __float_as_uint(ap[0]);
                af[mf][1] = __float_as_uint(ap[8 * ASTR]);
                af[mf][2] = __float_as_uint(ap[4]);
                af[mf][3] = __float_as_uint(ap[8 * ASTR + 4]);
            }
#pragma unroll
            for (int nf = 0; nf < 4; nf++) {
                const float* bp = bs + (nf * 8 + lr) * ASTR + s * 8 + lc;
                bf[nf][0] = __float_as_uint(bp[0]);
                bf[nf][1] = __float_as_uint(bp[4]);
            }
#pragma unroll
            for (int mf = 0; mf < 4; mf++)
#pragma unroll
                for (int nf = 0; nf < 4; nf++)
                    mma_tf32_16n8k8(acc[mf][nf], af[mf], bf[nf]);
        }
        __syncthreads();
    }

    // --- epilogue: scalar 4B stores (alignment-safe; sectors still filled
    //     by the pair of stores per fragment) ---
#pragma unroll
    for (int mf = 0; mf < 4; mf++) {
        const int row = m0 + wm * 64 + mf * 16 + lr;
#pragma unroll
        for (int nf = 0; nf < 4; nf++) {
            const int col = n0 + wn * 32 + nf * 8 + 2 * lc;
            float* c0p = C + (size_t)row * VOCAB + col;
            float* c2p = C + (size_t)(row + 8) * VOCAB + col;
            if (col + 1 < VOCAB) {
                c0p[0] = acc[mf][nf][0];
                c0p[1] = acc[mf][nf][1];
                c2p[0] = acc[mf][nf][2];
                c2p[1] = acc[mf][nf][3];
            } else if (col < VOCAB) {
                c0p[0] = acc[mf][nf][0];
                c2p[0] = acc[mf][nf][2];
            }
        }
    }
}

// ---------------------------------------------------------------------------
// Launch
// ---------------------------------------------------------------------------
extern "C" void kernel_launch(void* const* d_in, const int* in_sizes, int n_in,
                              void* d_out, int out_size) {
    const int*   idx   = (const int*)d_in[0];
    const float* Wemb  = (const float*)d_in[1];
    const float* G     = (const float*)d_in[2];
    const float* Win   = (const float*)d_in[3];
    const float* Wrec  = (const float*)d_in[4];
    const float* Wout  = (const float*)d_in[5];
    const float* gamma = (const float*)d_in[6];
    const float* beta  = (const float*)d_in[7];
    float* out = (float*)d_out;

    cudaFuncSetAttribute(k_gemm, cudaFuncAttributeMaxDynamicSharedMemorySize,
                         GEMM_SMEM);

    k_embed_route<<<NROWS / 8, 160>>>(idx, Wemb, G, Win);
    k_scan<<<1, 128>>>(Wrec);
    k_outln<<<NROWS, 256>>>(Wout, gamma, beta);

    float* hptr;
    cudaGetSymbolAddress((void**)&hptr, g_h);
    dim3 grid(NROWS / GTM, (VOCAB + GTN - 1) / GTN);   // (16, 393)
    k_gemm<<<grid, 256, GEMM_SMEM>>>(hptr, Wemb, out);
}